// round 16
// baseline (speedup 1.0000x reference)
#include <cuda_runtime.h>
#include <cstdint>

#define DIM    256
#define NQ     8
#define FFN    2048
#define EMBED  512
#define BS     32768                      // B * S
#define TOTAL_CH (BS * EMBED / 8)         // 2,097,152 32-byte chunks
#define BCTAS  1024                       // 1024*256*8 == TOTAL_CH exactly
#define CH_PER_ROW (EMBED / 8)            // 64 chunks per output row

// Scratch (device global — allocation-free per harness rules)
__device__ float g_o[EMBED];

// ---------------------------------------------------------------------------
// Kernel A (exact best-measured body): z -> h -> o.
// 64 CTAs x 256 threads; CTA b owns e = b*8 .. b*8+7.
// PDL trigger fires as soon as this CTA's g_o contribution is stored.
// ---------------------------------------------------------------------------
__global__ void k_fused_h_o(const float* __restrict__ U_re,
                            const float* __restrict__ U_im,
                            const float* __restrict__ W1,
                            const float* __restrict__ b1,
                            const float* __restrict__ W2,
                            const float* __restrict__ b2)
{
    __shared__ float  sp[DIM];         // probabilities
    __shared__ float  sz[NQ];          // z vector
    __shared__ float4 sh4[FFN / 4];    // full h, 8 KB

    const int t    = threadIdx.x;      // 0..255
    const int lane = t & 31;
    const int warp = t >> 5;           // 0..7

    // p_t = |U[t,0]|^2  (row stride DIM)
    {
        const float re = __ldg(&U_re[t * DIM]);
        const float im = __ldg(&U_im[t * DIM]);
        sp[t] = re * re + im * im;
    }
    __syncthreads();

    // warp q reduces qubit q: sign flips on bit (7-q) of state index s
    {
        const int bit = (NQ - 1) - warp;
        float v = 0.f;
        #pragma unroll
        for (int j = 0; j < 8; ++j) {
            const int s = lane + 32 * j;
            const float pv = sp[s];
            v += ((s >> bit) & 1) ? -pv : pv;
        }
        #pragma unroll
        for (int off = 16; off > 0; off >>= 1)
            v += __shfl_xor_sync(0xFFFFFFFFu, v, off);
        if (lane == 0) sz[warp] = v;
    }
    __syncthreads();

    const float z0 = sz[0], z1 = sz[1], z2 = sz[2], z3 = sz[3];
    const float z4 = sz[4], z5 = sz[5], z6 = sz[6], z7 = sz[7];

    // h rows t*8 .. t*8+7   (W1 is (FFN, 8) row-major)
    {
        const float4* __restrict__ w1v = (const float4*)(W1 + t * 8 * NQ);
        const float4 bb0 = __ldg((const float4*)(b1 + t * 8));
        const float4 bb1 = __ldg((const float4*)(b1 + t * 8 + 4));
        const float bias[8] = { bb0.x, bb0.y, bb0.z, bb0.w,
                                bb1.x, bb1.y, bb1.z, bb1.w };
        float hv[8];
        #pragma unroll
        for (int k = 0; k < 8; ++k) {
            const float4 a = __ldg(&w1v[k * 2]);
            const float4 b = __ldg(&w1v[k * 2 + 1]);
            float acc = bias[k];
            acc += z0*a.x + z1*a.y + z2*a.z + z3*a.w;
            acc += z4*b.x + z5*b.y + z6*b.z + z7*b.w;
            hv[k] = fmaxf(acc, 0.f);
        }
        sh4[t * 2]     = make_float4(hv[0], hv[1], hv[2], hv[3]);
        sh4[t * 2 + 1] = make_float4(hv[4], hv[5], hv[6], hv[7]);
    }
    __syncthreads();

    // o[e]: warp w -> e = blockIdx*8 + w
    const int e = blockIdx.x * 8 + warp;
    const float4* __restrict__ w2v = (const float4*)(W2 + (size_t)e * FFN);

    float acc = 0.f;
    #pragma unroll
    for (int i = lane; i < FFN / 4; i += 32) {
        const float4 w = __ldg(&w2v[i]);
        const float4 h = sh4[i];
        acc += w.x*h.x + w.y*h.y + w.z*h.z + w.w*h.w;
    }
    #pragma unroll
    for (int off = 16; off > 0; off >>= 1)
        acc += __shfl_xor_sync(0xFFFFFFFFu, acc, off);

    if (lane == 0) g_o[e] = acc + __ldg(&b2[e]);

    // PDL: this CTA's contribution is visible -> let the broadcast grid in.
    cudaTriggerProgrammaticLaunchCompletion();
}

// ---------------------------------------------------------------------------
// Kernel B (exact best-measured body): 256-bit stores, exact cover.
// 1024 CTAs x 256 thr x 8 STG.256. PDL: CTAs ramp up under kernel A's tail,
// then wait on the grid dependency before touching g_o.
// ---------------------------------------------------------------------------
__global__ void __launch_bounds__(256)
k_broadcast(float* __restrict__ out)
{
    __shared__ float so[EMBED];

    // address math before the dependency wait (overlaps kernel A)
    const unsigned c0  = blockIdx.x * 256u + threadIdx.x;
    const unsigned col = (c0 & (CH_PER_ROW - 1)) * 8u;
    float* p = out + (size_t)c0 * 8;
    const size_t stride_f = (size_t)BCTAS * 256 * 8;   // floats per step

    cudaGridDependencySynchronize();

    if (threadIdx.x < EMBED / 2) {
        so[threadIdx.x * 2]     = g_o[threadIdx.x * 2];
        so[threadIdx.x * 2 + 1] = g_o[threadIdx.x * 2 + 1];
    }
    __syncthreads();

    const float v0 = so[col + 0], v1 = so[col + 1];
    const float v2 = so[col + 2], v3 = so[col + 3];
    const float v4 = so[col + 4], v5 = so[col + 5];
    const float v6 = so[col + 6], v7 = so[col + 7];

    #pragma unroll
    for (int k = 0; k < 8; ++k) {
        asm volatile(
            "st.global.v8.f32 [%0], {%1, %2, %3, %4, %5, %6, %7, %8};"
            :: "l"(p + (size_t)k * stride_f),
               "f"(v0), "f"(v1), "f"(v2), "f"(v3),
               "f"(v4), "f"(v5), "f"(v6), "f"(v7)
            : "memory");
    }
}

// ---------------------------------------------------------------------------
extern "C" void kernel_launch(void* const* d_in, const int* in_sizes, int n_in,
                              void* d_out, int out_size)
{
    // metadata order: x, U_re, U_im, W1, b1, W2, b2  (x unused by the math)
    const float* U_re = (const float*)d_in[1];
    const float* U_im = (const float*)d_in[2];
    const float* W1   = (const float*)d_in[3];
    const float* b1   = (const float*)d_in[4];
    const float* W2   = (const float*)d_in[5];
    const float* b2   = (const float*)d_in[6];
    float*       out  = (float*)d_out;

    k_fused_h_o<<<EMBED / 8, 256>>>(U_re, U_im, W1, b1, W2, b2);

    // Broadcast with programmatic dependent launch (same stream the
    // harness captures).
    cudaLaunchConfig_t cfg = {};
    cfg.gridDim  = dim3(BCTAS);
    cfg.blockDim = dim3(256);
    cfg.dynamicSmemBytes = 0;
    cfg.stream = 0;

    cudaLaunchAttribute attr[1];
    attr[0].id = cudaLaunchAttributeProgrammaticStreamSerialization;
    attr[0].val.programmaticStreamSerializationAllowed = 1;
    cfg.attrs = attr;
    cfg.numAttrs = 1;

    cudaLaunchKernelEx(&cfg, k_broadcast, out);
}